// round 6
// baseline (speedup 1.0000x reference)
#include <cuda_runtime.h>
#include <cuda_bf16.h>
#include <math.h>
#include <stdint.h>

// ---------------- problem constants ----------------
#define BB 8
#define NN 1024
#define DV 768
#define DS 512
#define FF 768
#define HH 12
#define DH 64
#define KG 1280        // Dv + Ds
#define ROWS (BB*NN)   // 8192
#define SCALE 0.125f   // dh^-0.5
#define EPS 1e-5f

// ---------------- scratch (device globals; no allocation allowed) ----------------
__device__ float g_q[BB*FF];
__device__ float g_gw[BB*HH*DV];      // scale * gv[d] * wqk[b,h,d]
__device__ float g_S1[BB*HH];         // sum_d gw
__device__ float g_S0[BB*HH];         // scale * sum_d bv[d]*wqk
__device__ float g_gsem[BB*DV];       // sem @ Wg[:,768:].T + bg
__device__ float g_mu[ROWS];
__device__ float g_rstd[ROWS];
__device__ float g_scores[BB*HH*NN];
__device__ float g_w[BB*HH*NN];       // attn * rstd
__device__ float g_t[BB*HH];          // sum_n attn*rstd*mu
#define NCHUNK 32
__device__ float g_vbarp[NCHUNK*BB*HH*DV];
__device__ float g_vbar[BB*HH*DV];
__device__ float g_ctx[BB*FF];
__device__ float g_att[BB*DV];
__device__ __nv_bfloat16 g_Abf[ROWS*DV];   // bf16 copy of visual (written by k1)
__device__ __nv_bfloat16 g_Bbf[DV*DV];     // bf16 copy of Wg[:, :768]

// ---------------- generic helpers ----------------
__device__ __forceinline__ float warp_sum(float v) {
#pragma unroll
    for (int o = 16; o > 0; o >>= 1) v += __shfl_down_sync(0xffffffffu, v, o);
    return v;
}
__device__ __forceinline__ float warp_sum_all(float v) {
#pragma unroll
    for (int o = 16; o > 0; o >>= 1) v += __shfl_xor_sync(0xffffffffu, v, o);
    return v;
}
__device__ __forceinline__ float warp_max(float v) {
#pragma unroll
    for (int o = 16; o > 0; o >>= 1) v = fmaxf(v, __shfl_down_sync(0xffffffffu, v, o));
    return v;
}
__device__ __forceinline__ float block_sum256(float v, float* red) {
    int lane = threadIdx.x & 31, wid = threadIdx.x >> 5;
    __syncthreads();
    v = warp_sum(v);
    if (lane == 0) red[wid] = v;
    __syncthreads();
    if (wid == 0) {
        float x = (lane < 8) ? red[lane] : 0.f;
        x = warp_sum(x);
        if (lane == 0) red[0] = x;
    }
    __syncthreads();
    return red[0];
}
__device__ __forceinline__ float block_max256(float v, float* red) {
    int lane = threadIdx.x & 31, wid = threadIdx.x >> 5;
    __syncthreads();
    v = warp_max(v);
    if (lane == 0) red[wid] = v;
    __syncthreads();
    if (wid == 0) {
        float x = (lane < 8) ? red[lane] : -1e30f;
        x = warp_max(x);
        if (lane == 0) red[0] = x;
    }
    __syncthreads();
    return red[0];
}

#define CP16(dst, src)   asm volatile("cp.async.cg.shared.global [%0], [%1], 16;" :: "r"(dst), "l"(src) : "memory")
#define CP_COMMIT()      asm volatile("cp.async.commit_group;" ::: "memory")

__device__ __forceinline__ uint32_t smem_u32(const void* p) {
    uint32_t a;
    asm("{ .reg .u64 t; cvta.to.shared.u64 t, %1; cvt.u32.u64 %0, t; }" : "=r"(a) : "l"(p));
    return a;
}

// m16n8k16 bf16 mma (row.col), D = A*B + D, fp32 accumulate.
__device__ __forceinline__ void mma_bf16(float* c, const uint32_t* a, const uint32_t* b) {
    asm volatile(
        "mma.sync.aligned.m16n8k16.row.col.f32.bf16.bf16.f32 "
        "{%0,%1,%2,%3}, {%4,%5,%6,%7}, {%8,%9}, {%0,%1,%2,%3};"
        : "+f"(c[0]), "+f"(c[1]), "+f"(c[2]), "+f"(c[3])
        : "r"(a[0]), "r"(a[1]), "r"(a[2]), "r"(a[3]), "r"(b[0]), "r"(b[1]));
}
__device__ __forceinline__ void ldmat4(uint32_t* r, uint32_t addr) {
    asm volatile("ldmatrix.sync.aligned.m8n8.x4.shared.b16 {%0,%1,%2,%3}, [%4];"
        : "=r"(r[0]), "=r"(r[1]), "=r"(r[2]), "=r"(r[3]) : "r"(addr));
}

// ---------------- K0a: semantic LN + q = sem_n @ Wq.T ----------------
__global__ __launch_bounds__(256) void k0a(const float* __restrict__ sem,
                                           const float* __restrict__ Wq,
                                           const float* __restrict__ gs,
                                           const float* __restrict__ bs) {
    int b = blockIdx.x;
    __shared__ float sm[DS];
    __shared__ float red[8];
    int tid = threadIdx.x, lane = tid & 31, wid = tid >> 5;
    float sum = 0.f, sq = 0.f;
    for (int i = tid; i < DS; i += 256) {
        float v = sem[b*DS + i];
        sm[i] = v; sum += v; sq += v*v;
    }
    sum = block_sum256(sum, red);
    sq  = block_sum256(sq, red);
    float mu = sum * (1.f/DS);
    float rstd = rsqrtf(sq * (1.f/DS) - mu*mu + EPS);
    for (int i = tid; i < DS; i += 256)
        sm[i] = (sm[i] - mu) * rstd * gs[i] + bs[i];
    __syncthreads();
    for (int f = wid; f < FF; f += 8) {
        float dot = 0.f;
        for (int s = lane; s < DS; s += 32) dot += sm[s] * Wq[(size_t)f*DS + s];
        dot = warp_sum(dot);
        if (lane == 0) g_q[b*FF + f] = dot;
    }
}

// ---------------- K0b: gw[b,h,:] = scale*gv*(q_h @ Wk_h), S1, S0 ----------------
__global__ __launch_bounds__(256) void k0b(const float* __restrict__ Wk,
                                           const float* __restrict__ gv,
                                           const float* __restrict__ bv) {
    int h = blockIdx.x, b = blockIdx.y;
    __shared__ float qh[DH];
    __shared__ float red[8];
    int tid = threadIdx.x;
    if (tid < DH) qh[tid] = g_q[b*FF + h*DH + tid];
    __syncthreads();
    float s1p = 0.f, s0p = 0.f;
    for (int d = tid; d < DV; d += 256) {
        float s = 0.f;
#pragma unroll 16
        for (int j = 0; j < DH; j++) s += qh[j] * Wk[(size_t)(h*DH + j)*DV + d];
        s *= SCALE;
        float gwv = gv[d] * s;
        g_gw[(b*HH + h)*DV + d] = gwv;
        s1p += gwv;
        s0p += bv[d] * s;
    }
    s1p = block_sum256(s1p, red);
    s0p = block_sum256(s0p, red);
    if (tid == 0) { g_S1[b*HH + h] = s1p; g_S0[b*HH + h] = s0p; }
}

// ---------------- K0c: gsem[b,:] = sem @ Wg[:,768:].T + bg ----------------
__global__ __launch_bounds__(256) void k0c(const float* __restrict__ sem,
                                           const float* __restrict__ Wg,
                                           const float* __restrict__ bg) {
    int b = blockIdx.x;
    __shared__ float sm[DS];
    int tid = threadIdx.x, lane = tid & 31, wid = tid >> 5;
    for (int i = tid; i < DS; i += 256) sm[i] = sem[b*DS + i];
    __syncthreads();
    for (int dv = wid; dv < DV; dv += 8) {
        float dot = 0.f;
        for (int s = lane; s < DS; s += 32) dot += sm[s] * Wg[(size_t)dv*KG + DV + s];
        dot = warp_sum(dot);
        if (lane == 0) g_gsem[b*DV + dv] = dot + bg[dv];
    }
}

// ---------------- Kcb: convert Wg[:, :768] to bf16 ----------------
__global__ __launch_bounds__(256) void kcb(const float* __restrict__ Wg) {
    int idx = blockIdx.x * 256 + threadIdx.x;     // 768*192 = 147456 float4
    if (idx >= DV*192) return;
    int row = idx / 192, j = idx % 192;
    float4 v = *(const float4*)(Wg + (size_t)row*KG + j*4);
    __nv_bfloat162* dst = (__nv_bfloat162*)(g_Bbf + (size_t)row*DV + j*4);
    dst[0] = __floats2bfloat162_rn(v.x, v.y);
    dst[1] = __floats2bfloat162_rn(v.z, v.w);
}

// ---------------- K1: LN stats + scores + bf16 emit (32 rows / block) ----------------
__global__ __launch_bounds__(256, 2) void k1(const float* __restrict__ vis) {
    __shared__ float gw_s[HH*DV];   // 36 KB
    __shared__ float s1s[HH], s0s[HH];
    int tid = threadIdx.x, lane = tid & 31, wid = tid >> 5;
    int row0 = blockIdx.x * 32;
    int b = row0 >> 10;
    {
        const float4* gsrc = (const float4*)(g_gw + b*HH*DV);
        float4* gdst = (float4*)gw_s;
#pragma unroll
        for (int i = 0; i < 9; i++) gdst[tid + i*256] = gsrc[tid + i*256];
    }
    if (tid < HH) { s1s[tid] = g_S1[b*HH + tid]; s0s[tid] = g_S0[b*HH + tid]; }
    __syncthreads();
#pragma unroll
    for (int rr = 0; rr < 4; rr++) {
        int row = row0 + wid*4 + rr;
        const float4* x4 = (const float4*)(vis + (size_t)row * DV);
        float4 xv[6];
#pragma unroll
        for (int s = 0; s < 6; s++) xv[s] = x4[s*32 + lane];
        // emit bf16 copy for the gate GEMM
#pragma unroll
        for (int s = 0; s < 6; s++) {
            __nv_bfloat162* dst = (__nv_bfloat162*)(g_Abf + (size_t)row*DV + s*128 + lane*4);
            dst[0] = __floats2bfloat162_rn(xv[s].x, xv[s].y);
            dst[1] = __floats2bfloat162_rn(xv[s].z, xv[s].w);
        }
        float sum = 0.f, sq = 0.f;
#pragma unroll
        for (int s = 0; s < 6; s++) {
            sum += xv[s].x + xv[s].y + xv[s].z + xv[s].w;
            sq  += xv[s].x*xv[s].x + xv[s].y*xv[s].y + xv[s].z*xv[s].z + xv[s].w*xv[s].w;
        }
        sum = warp_sum_all(sum);
        sq  = warp_sum_all(sq);
        float mu = sum * (1.f/DV);
        float rstd = rsqrtf(sq * (1.f/DV) - mu*mu + EPS);
        if (lane == 0) { g_mu[row] = mu; g_rstd[row] = rstd; }
        int n = row & (NN - 1);
#pragma unroll 2
        for (int h = 0; h < HH; h++) {
            const float4* g4 = (const float4*)(gw_s + h*DV);
            float dot = 0.f;
#pragma unroll
            for (int s = 0; s < 6; s++) {
                float4 gv4 = g4[s*32 + lane];
                dot += xv[s].x*gv4.x + xv[s].y*gv4.y + xv[s].z*gv4.z + xv[s].w*gv4.w;
            }
            dot = warp_sum(dot);
            if (lane == 0)
                g_scores[(b*HH + h)*NN + n] = rstd * (dot - mu*s1s[h]) + s0s[h];
        }
    }
}

// ---------------- K2: softmax over n; w = attn*rstd, t = sum attn*rstd*mu ----------------
__global__ __launch_bounds__(256) void k2() {
    int bh = blockIdx.x;
    int b = bh / HH;
    __shared__ float red[8];
    int tid = threadIdx.x;
    float loc[4];
    float mx = -1e30f;
#pragma unroll
    for (int i = 0; i < 4; i++) {
        loc[i] = g_scores[bh*NN + tid + i*256];
        mx = fmaxf(mx, loc[i]);
    }
    mx = block_max256(mx, red);
    float s = 0.f;
#pragma unroll
    for (int i = 0; i < 4; i++) { loc[i] = expf(loc[i] - mx); s += loc[i]; }
    s = block_sum256(s, red);
    float inv = 1.f / s;
    float tp = 0.f;
#pragma unroll
    for (int i = 0; i < 4; i++) {
        int n = tid + i*256;
        float a = loc[i] * inv;
        float rs = g_rstd[b*NN + n];
        float w = a * rs;
        g_w[bh*NN + n] = w;
        tp += w * g_mu[b*NN + n];
    }
    tp = block_sum256(tp, red);
    if (tid == 0) g_t[bh] = tp;
}

// ---------------- K3: per-chunk partial vbar (deterministic) ----------------
__global__ __launch_bounds__(768) void k3(const float* __restrict__ vis) {
    int chunk = blockIdx.x;     // 32 chunks of 32 tokens
    int b = blockIdx.y;
    int d = threadIdx.x;        // 768 threads = one per feature
    __shared__ float ws[HH][32];
    int n0 = chunk * 32;
    if (d < HH*32) {
        int h = d >> 5, j = d & 31;
        ws[h][j] = g_w[(b*HH + h)*NN + n0 + j];
    }
    __syncthreads();
    float acc[HH];
#pragma unroll
    for (int h = 0; h < HH; h++) acc[h] = 0.f;
    const float* base = vis + ((size_t)(b << 10) + n0) * DV + d;
#pragma unroll 4
    for (int j = 0; j < 32; j++) {
        float x = base[(size_t)j * DV];
#pragma unroll
        for (int h = 0; h < HH; h++) acc[h] += ws[h][j] * x;
    }
#pragma unroll
    for (int h = 0; h < HH; h++)
        g_vbarp[(size_t)chunk*(BB*HH*DV) + (b*HH + h)*DV + d] = acc[h];
}

// ---------------- K3b: reduce chunks ----------------
__global__ __launch_bounds__(1024) void k3b() {
    int i = blockIdx.x * 1024 + threadIdx.x;
    float s = 0.f;
#pragma unroll
    for (int c = 0; c < NCHUNK; c++) s += g_vbarp[(size_t)c*(BB*HH*DV) + i];
    g_vbar[i] = s;
}

// ---------------- K4a: ctx[b,f] = u[b,h,:] @ Wv[f,:] ----------------
__global__ __launch_bounds__(256) void k4a(const float* __restrict__ Wv,
                                           const float* __restrict__ gv,
                                           const float* __restrict__ bv) {
    int h = blockIdx.x, b = blockIdx.y;
    __shared__ float u[DV];
    int tid = threadIdx.x, lane = tid & 31, wid = tid >> 5;
    float t = g_t[b*HH + h];
    for (int d = tid; d < DV; d += 256)
        u[d] = gv[d] * (g_vbar[(b*HH + h)*DV + d] - t) + bv[d];
    __syncthreads();
    for (int j = wid; j < DH; j += 8) {
        int f = h*DH + j;
        float dot = 0.f;
        for (int d = lane; d < DV; d += 32) dot += u[d] * Wv[(size_t)f*DV + d];
        dot = warp_sum(dot);
        if (lane == 0) g_ctx[b*FF + f] = dot;
    }
}

// ---------------- K4b: attended[b,:] = ctx @ Wo.T + bo ----------------
__global__ __launch_bounds__(256) void k4b(const float* __restrict__ Wo,
                                           const float* __restrict__ bo) {
    int b = blockIdx.x;
    __shared__ float c[FF];
    int tid = threadIdx.x, lane = tid & 31, wid = tid >> 5;
    for (int i = tid; i < FF; i += 256) c[i] = g_ctx[b*FF + i];
    __syncthreads();
    for (int dv = wid; dv < DV; dv += 8) {
        float dot = 0.f;
        for (int f = lane; f < FF; f += 32) dot += c[f] * Wo[(size_t)dv*FF + f];
        dot = warp_sum(dot);
        if (lane == 0) g_att[b*DV + dv] = dot + bo[dv];
    }
}

// ---------------- K5: gate GEMM (bf16 mma + ldmatrix) + fused epilogue ----------------
// out[r,c] = A[r,c] + sigmoid( logit[r,c] + gsem[b,c] ) * att[b,c]
// CTA tile M=128, N=128; K=768 in 12 chunks of 64 bf16 (4 k16-steps each).
// 3-stage cp.async pipeline. 8 warps 2(M)x4(N), warp 64x32 via m16n8k16.
// smem tile row = 64 bf16 = 128B, XOR-swizzled 16B units: phys = row*128 + ((seg^(row&7))*16)
// -> ldmatrix phases (8 rows, same k) hit 8 distinct 16B banks: conflict-free.

#define K5_STAGE 32768u                    // A 16KB + B 16KB
#define K5_AOFF(s) ((uint32_t)(s)*K5_STAGE)
#define K5_BOFF(s) ((uint32_t)(s)*K5_STAGE + 16384u)
#define K5_SMEM_TOTAL 98304                // 3 stages; C staging (67.6KB) reuses it
#define K5_CS 132

__global__ void __launch_bounds__(256, 2)
k5(const float* __restrict__ Avis, float* __restrict__ out) {
    extern __shared__ float smem[];
    uint32_t sbase = smem_u32(smem);
    int tid = threadIdx.x, wid = tid >> 5, lane = tid & 31;
    int rowBase = blockIdx.x * 128;
    int colBase = blockIdx.y * 128;
    int warp_m = wid >> 2;       // 0..1 -> 64 rows
    int warp_n = wid & 3;        // 0..3 -> 32 cols

    // cp.async slots: 4 x 16B for A + 4 for B per chunk
    uint32_t dsto[4];
    const __nv_bfloat16* srcA[4];
    const __nv_bfloat16* srcB[4];
#pragma unroll
    for (int i = 0; i < 4; i++) {
        int idx = tid + i*256;           // 0..1023
        int row = idx >> 3, seg = idx & 7;
        dsto[i] = (uint32_t)(row*128 + ((seg ^ (row & 7))*16));
        srcA[i] = g_Abf + (size_t)(rowBase + row)*DV + seg*8;
        srcB[i] = g_Bbf + (size_t)(colBase + row)*DV + seg*8;
    }

    // ldmatrix lane geometry
    int i8 = lane & 7, q = lane >> 3;
    uint32_t aRow[4], bRow[2];
#pragma unroll
    for (int mi = 0; mi < 4; mi++)
        aRow[mi] = (uint32_t)((warp_m*64 + mi*16 + i8 + (q & 1)*8) * 128);
#pragma unroll
    for (int bp = 0; bp < 2; bp++)
        bRow[bp] = (uint32_t)((warp_n*32 + bp*16 + i8 + (q >> 1)*8) * 128);
    int xr = i8*4;
    int kqa = (q >> 1)*4;    // A: k8-half select
    int kqb = (q & 1)*4;     // B: k8-half select

    float cf[4][4][4];
#pragma unroll
    for (int mi = 0; mi < 4; mi++)
#pragma unroll
        for (int ni = 0; ni < 4; ni++)
#pragma unroll
            for (int e = 0; e < 4; e++) cf[mi][ni][e] = 0.f;

    // prologue: chunks 0,1
#pragma unroll
    for (int c = 0; c < 2; c++) {
#pragma unroll
        for (int i = 0; i < 4; i++) {
            CP16(sbase + K5_AOFF(c) + dsto[i], srcA[i] + c*64);
            CP16(sbase + K5_BOFF(c) + dsto[i], srcB[i] + c*64);
        }
        CP_COMMIT();
    }

    for (int kt = 0; kt < 12; kt++) {
        int buf = kt % 3;
        if (kt < 11) asm volatile("cp.async.wait_group 1;" ::: "memory");
        else         asm volatile("cp.async.wait_group 0;" ::: "memory");
        __syncthreads();

        if (kt + 2 < 12) {
            int nb = (kt + 2) % 3;
#pragma unroll
            for (int i = 0; i < 4; i++) {
                CP16(sbase + K5_AOFF(nb) + dsto[i], srcA[i] + (kt+2)*64);
                CP16(sbase + K5_BOFF(nb) + dsto[i], srcB[i] + (kt+2)*64);
            }
            CP_COMMIT();
        }

        uint32_t Ab = sbase + K5_AOFF(buf);
        uint32_t Bb = sbase + K5_BOFF(buf);
#pragma unroll
        for (int ks = 0; ks < 4; ks++) {
            uint32_t aoffk = (uint32_t)(((ks*8 + kqa) ^ xr) << 2);
            uint32_t boffk = (uint32_t)(((ks*8 + kqb) ^ xr) << 2);
            uint32_t af[4][4], bb[2][4];
#pragma unroll
            for (int mi = 0; mi < 4; mi++) ldmat4(af[mi], Ab + aRow[mi] + aoffk);
#pragma unroll
            for (int bp = 0; bp < 2; bp++) ldmat4(bb[bp], Bb + bRow[bp] + boffk);
            // bb[bp] = {b0(ni=2bp), b1(2bp), b0(2bp+1), b1(2bp+1)}
#pragma unroll
            for (int mi = 0; mi < 4; mi++)
#pragma unroll
                for (int ni = 0; ni < 4; ni++)
                    mma_bf16(cf[mi][ni], af[mi], &bb[ni >> 1][(ni & 1)*2]);
        }
    }
    __syncthreads();

    // stage accumulators into smem (reuses pipeline smem)
    int g = lane >> 2, tig = lane & 3;
#pragma unroll
    for (int mi = 0; mi < 4; mi++) {
        int r0 = warp_m*64 + mi*16 + g;
#pragma unroll
        for (int ni = 0; ni < 4; ni++) {
            int c0 = warp_n*32 + ni*8 + 2*tig;
            smem[r0*K5_CS + c0]         = cf[mi][ni][0];
            smem[r0*K5_CS + c0 + 1]     = cf[mi][ni][1];
            smem[(r0+8)*K5_CS + c0]     = cf[mi][ni][2];
            smem[(r0+8)*K5_CS + c0 + 1] = cf[mi][ni][3];
        }
    }
    __syncthreads();

    // fused epilogue: 4096 float4, 16 per thread; residual from fp32 visual
    int b = rowBase >> 10;
    const float* gs = g_gsem + b*DV;
    const float* at = g_att + b*DV;
#pragma unroll
    for (int j = 0; j < 16; j++) {
        int idx = tid + j*256;          // float4 index
        int row = idx >> 5, c4 = idx & 31;
        int r = rowBase + row;
        int c = colBase + c4*4;
        const float* Cr = smem + row*K5_CS + c4*4;
        float4 av = *(const float4*)(Avis + (size_t)r*DV + c);
        float4 o;
        o.x = av.x + at[c+0] * (1.f/(1.f + __expf(-(Cr[0] + gs[c+0]))));
        o.y = av.y + at[c+1] * (1.f/(1.f + __expf(-(Cr[1] + gs[c+1]))));
        o.z = av.z + at[c+2] * (1.f/(1.f + __expf(-(Cr[2] + gs[c+2]))));
        o.w = av.w + at[c+3] * (1.f/(1.f + __expf(-(Cr[3] + gs[c+3]))));
        *(float4*)(out + (size_t)r*DV + c) = o;
    }
}

// ---------------- launcher ----------------
extern "C" void kernel_launch(void* const* d_in, const int* in_sizes, int n_in,
                              void* d_out, int out_size) {
    const float* visual   = (const float*)d_in[0];
    const float* semantic = (const float*)d_in[1];
    const float* Wq = (const float*)d_in[2];
    const float* Wk = (const float*)d_in[3];
    const float* Wv = (const float*)d_in[4];
    const float* Wo = (const float*)d_in[5];
    const float* bo = (const float*)d_in[6];
    const float* Wg = (const float*)d_in[7];
    const float* bg = (const float*)d_in[8];
    const float* gv = (const float*)d_in[9];
    const float* bv = (const float*)d_in[10];
    const float* gs = (const float*)d_in[11];
    const float* bs = (const float*)d_in[12];
    float* out = (float*)d_out;

    cudaFuncSetAttribute(k5, cudaFuncAttributeMaxDynamicSharedMemorySize, K5_SMEM_TOTAL);

    k0a<<<BB, 256>>>(semantic, Wq, gs, bs);
    k0b<<<dim3(HH, BB), 256>>>(Wk, gv, bv);
    k0c<<<BB, 256>>>(semantic, Wg, bg);
    kcb<<<576, 256>>>(Wg);
    k1<<<ROWS/32, 256>>>(visual);
    k2<<<BB*HH, 256>>>();
    k3<<<dim3(NCHUNK, BB), 768>>>(visual);
    k3b<<<(BB*HH*DV)/1024, 1024>>>();
    k4a<<<dim3(HH, BB), 256>>>(Wv, gv, bv);
    k4b<<<BB, 256>>>(Wo, bo);
    k5<<<dim3(ROWS/128, DV/128), 256, K5_SMEM_TOTAL>>>(visual, out);
}

// round 7
// speedup vs baseline: 1.5499x; 1.5499x over previous
#include <cuda_runtime.h>
#include <math.h>
#include <stdint.h>

// ---------------- problem constants ----------------
#define BB 8
#define NN 1024
#define DV 768
#define DS 512
#define FF 768
#define HH 12
#define DH 64
#define KG 1280        // Dv + Ds
#define ROWS (BB*NN)   // 8192
#define SCALE 0.125f   // dh^-0.5
#define EPS 1e-5f

// ---------------- scratch (device globals; no allocation allowed) ----------------
__device__ float g_gw[BB*HH*DV];      // scale * gv[d] * wqk[b,h,d]
__device__ float g_S1[BB*HH];         // sum_d gw
__device__ float g_S0[BB*HH];         // scale * sum_d bv[d]*wqk
__device__ float g_gsem[BB*DV];       // sem @ Wg[:,768:].T + bg
__device__ float g_mu[ROWS];
__device__ float g_rstd[ROWS];
__device__ float g_scores[BB*HH*NN];
__device__ float g_w[BB*HH*NN];       // attn * rstd
__device__ float g_t[BB*HH];          // sum_n attn*rstd*mu
#define NCHUNK 32
__device__ float g_vbarp[NCHUNK*BB*HH*DV];
__device__ float g_ctx[BB*FF];
__device__ float g_att[BB*DV];

// ---------------- generic helpers ----------------
__device__ __forceinline__ float warp_sum(float v) {
#pragma unroll
    for (int o = 16; o > 0; o >>= 1) v += __shfl_down_sync(0xffffffffu, v, o);
    return v;
}
__device__ __forceinline__ float warp_sum_all(float v) {
#pragma unroll
    for (int o = 16; o > 0; o >>= 1) v += __shfl_xor_sync(0xffffffffu, v, o);
    return v;
}
__device__ __forceinline__ float warp_max(float v) {
#pragma unroll
    for (int o = 16; o > 0; o >>= 1) v = fmaxf(v, __shfl_down_sync(0xffffffffu, v, o));
    return v;
}
__device__ __forceinline__ float block_sum256(float v, float* red) {
    int lane = threadIdx.x & 31, wid = threadIdx.x >> 5;
    __syncthreads();
    v = warp_sum(v);
    if (lane == 0) red[wid] = v;
    __syncthreads();
    if (wid == 0) {
        float x = (lane < 8) ? red[lane] : 0.f;
        x = warp_sum(x);
        if (lane == 0) red[0] = x;
    }
    __syncthreads();
    return red[0];
}
__device__ __forceinline__ float block_max256(float v, float* red) {
    int lane = threadIdx.x & 31, wid = threadIdx.x >> 5;
    __syncthreads();
    v = warp_max(v);
    if (lane == 0) red[wid] = v;
    __syncthreads();
    if (wid == 0) {
        float x = (lane < 8) ? red[lane] : -1e30f;
        x = warp_max(x);
        if (lane == 0) red[0] = x;
    }
    __syncthreads();
    return red[0];
}

#define CP16(dst, src)   asm volatile("cp.async.cg.shared.global [%0], [%1], 16;" :: "r"(dst), "l"(src) : "memory")
#define CP_COMMIT()      asm volatile("cp.async.commit_group;" ::: "memory")

__device__ __forceinline__ uint32_t smem_u32(const void* p) {
    uint32_t a;
    asm("{ .reg .u64 t; cvta.to.shared.u64 t, %1; cvt.u32.u64 %0, t; }" : "=r"(a) : "l"(p));
    return a;
}

// m16n8k8 tf32 mma (row.col), D = A*B + D. Operands hold raw fp32 bits
// (HW consumes the tf32 subset; truncation error ~2^-10, far under tolerance).
__device__ __forceinline__ void mma_tf32(float* c, const uint32_t* a, const uint32_t* b) {
    asm volatile(
        "mma.sync.aligned.m16n8k8.row.col.f32.tf32.tf32.f32 "
        "{%0,%1,%2,%3}, {%4,%5,%6,%7}, {%8,%9}, {%0,%1,%2,%3};"
        : "+f"(c[0]), "+f"(c[1]), "+f"(c[2]), "+f"(c[3])
        : "r"(a[0]), "r"(a[1]), "r"(a[2]), "r"(a[3]), "r"(b[0]), "r"(b[1]));
}

// ---------------- K0 (fused k0a+k0b+k0c) ----------------
// blocks 0..95: (b,h) = (blk/12, blk%12): LN(sem) -> q_h -> gw/S1/S0
// blocks 96..103: b = blk-96: gsem = sem @ Wg[:,768:].T + bg
__global__ __launch_bounds__(256) void k0(const float* __restrict__ sem,
                                          const float* __restrict__ Wq,
                                          const float* __restrict__ Wk,
                                          const float* __restrict__ Wg,
                                          const float* __restrict__ gv,
                                          const float* __restrict__ bv,
                                          const float* __restrict__ gs,
                                          const float* __restrict__ bs,
                                          const float* __restrict__ bg) {
    int blk = blockIdx.x;
    int tid = threadIdx.x, lane = tid & 31, wid = tid >> 5;
    __shared__ float sm[DS];
    __shared__ float red[8];
    __shared__ float qh[DH];
    if (blk < 96) {
        int b = blk / 12, h = blk % 12;
        float sum = 0.f, sq = 0.f;
        for (int i = tid; i < DS; i += 256) {
            float v = sem[b*DS + i];
            sm[i] = v; sum += v; sq += v*v;
        }
        sum = block_sum256(sum, red);
        sq  = block_sum256(sq, red);
        float mu = sum * (1.f/DS);
        float rstd = rsqrtf(sq * (1.f/DS) - mu*mu + EPS);
        for (int i = tid; i < DS; i += 256)
            sm[i] = (sm[i] - mu) * rstd * gs[i] + bs[i];
        __syncthreads();
        // q_h (64 outputs), 8 per warp
        for (int j = wid; j < DH; j += 8) {
            int f = h*DH + j;
            float dot = 0.f;
            for (int s = lane; s < DS; s += 32) dot += sm[s] * Wq[(size_t)f*DS + s];
            dot = warp_sum(dot);
            if (lane == 0) qh[j] = dot;
        }
        __syncthreads();
        float s1p = 0.f, s0p = 0.f;
        for (int d = tid; d < DV; d += 256) {
            float s = 0.f;
#pragma unroll 16
            for (int j = 0; j < DH; j++) s += qh[j] * Wk[(size_t)(h*DH + j)*DV + d];
            s *= SCALE;
            float gwv = gv[d] * s;
            g_gw[(b*HH + h)*DV + d] = gwv;
            s1p += gwv;
            s0p += bv[d] * s;
        }
        s1p = block_sum256(s1p, red);
        s0p = block_sum256(s0p, red);
        if (tid == 0) { g_S1[b*HH + h] = s1p; g_S0[b*HH + h] = s0p; }
    } else {
        int b = blk - 96;
        for (int i = tid; i < DS; i += 256) sm[i] = sem[b*DS + i];
        __syncthreads();
        for (int dv = wid; dv < DV; dv += 8) {
            float dot = 0.f;
            for (int s = lane; s < DS; s += 32) dot += sm[s] * Wg[(size_t)dv*KG + DV + s];
            dot = warp_sum(dot);
            if (lane == 0) g_gsem[b*DV + dv] = dot + bg[dv];
        }
    }
}

// ---------------- K1: warp-per-row LN stats + scores (32 rows / block) ----------------
__global__ __launch_bounds__(256, 2) void k1(const float* __restrict__ vis) {
    __shared__ float gw_s[HH*DV];   // 36 KB
    __shared__ float s1s[HH], s0s[HH];
    int tid = threadIdx.x, lane = tid & 31, wid = tid >> 5;
    int row0 = blockIdx.x * 32;
    int b = row0 >> 10;
    {
        const float4* gsrc = (const float4*)(g_gw + b*HH*DV);
        float4* gdst = (float4*)gw_s;
#pragma unroll
        for (int i = 0; i < 9; i++) gdst[tid + i*256] = gsrc[tid + i*256];
    }
    if (tid < HH) { s1s[tid] = g_S1[b*HH + tid]; s0s[tid] = g_S0[b*HH + tid]; }
    __syncthreads();
#pragma unroll
    for (int rr = 0; rr < 4; rr++) {
        int row = row0 + wid*4 + rr;
        const float4* x4 = (const float4*)(vis + (size_t)row * DV);
        float4 xv[6];
#pragma unroll
        for (int s = 0; s < 6; s++) xv[s] = x4[s*32 + lane];
        float sum = 0.f, sq = 0.f;
#pragma unroll
        for (int s = 0; s < 6; s++) {
            sum += xv[s].x + xv[s].y + xv[s].z + xv[s].w;
            sq  += xv[s].x*xv[s].x + xv[s].y*xv[s].y + xv[s].z*xv[s].z + xv[s].w*xv[s].w;
        }
        sum = warp_sum_all(sum);
        sq  = warp_sum_all(sq);
        float mu = sum * (1.f/DV);
        float rstd = rsqrtf(sq * (1.f/DV) - mu*mu + EPS);
        if (lane == 0) { g_mu[row] = mu; g_rstd[row] = rstd; }
        int n = row & (NN - 1);
#pragma unroll 2
        for (int h = 0; h < HH; h++) {
            const float4* g4 = (const float4*)(gw_s + h*DV);
            float dot = 0.f;
#pragma unroll
            for (int s = 0; s < 6; s++) {
                float4 gv4 = g4[s*32 + lane];
                dot += xv[s].x*gv4.x + xv[s].y*gv4.y + xv[s].z*gv4.z + xv[s].w*gv4.w;
            }
            dot = warp_sum(dot);
            if (lane == 0)
                g_scores[(b*HH + h)*NN + n] = rstd * (dot - mu*s1s[h]) + s0s[h];
        }
    }
}

// ---------------- K2: softmax over n; w = attn*rstd, t = sum attn*rstd*mu ----------------
__global__ __launch_bounds__(256) void k2() {
    int bh = blockIdx.x;
    int b = bh / HH;
    __shared__ float red[8];
    int tid = threadIdx.x;
    float loc[4];
    float mx = -1e30f;
#pragma unroll
    for (int i = 0; i < 4; i++) {
        loc[i] = g_scores[bh*NN + tid + i*256];
        mx = fmaxf(mx, loc[i]);
    }
    mx = block_max256(mx, red);
    float s = 0.f;
#pragma unroll
    for (int i = 0; i < 4; i++) { loc[i] = expf(loc[i] - mx); s += loc[i]; }
    s = block_sum256(s, red);
    float inv = 1.f / s;
    float tp = 0.f;
#pragma unroll
    for (int i = 0; i < 4; i++) {
        int n = tid + i*256;
        float a = loc[i] * inv;
        float rs = g_rstd[b*NN + n];
        float w = a * rs;
        g_w[bh*NN + n] = w;
        tp += w * g_mu[b*NN + n];
    }
    tp = block_sum256(tp, red);
    if (tid == 0) g_t[bh] = tp;
}

// ---------------- K3: per-chunk partial vbar (deterministic) ----------------
__global__ __launch_bounds__(768) void k3(const float* __restrict__ vis) {
    int chunk = blockIdx.x;     // 32 chunks of 32 tokens
    int b = blockIdx.y;
    int d = threadIdx.x;        // 768 threads = one per feature
    __shared__ float ws[HH][32];
    int n0 = chunk * 32;
    if (d < HH*32) {
        int h = d >> 5, j = d & 31;
        ws[h][j] = g_w[(b*HH + h)*NN + n0 + j];
    }
    __syncthreads();
    float acc[HH];
#pragma unroll
    for (int h = 0; h < HH; h++) acc[h] = 0.f;
    const float* base = vis + ((size_t)(b << 10) + n0) * DV + d;
#pragma unroll 4
    for (int j = 0; j < 32; j++) {
        float x = base[(size_t)j * DV];
#pragma unroll
        for (int h = 0; h < HH; h++) acc[h] += ws[h][j] * x;
    }
#pragma unroll
    for (int h = 0; h < HH; h++)
        g_vbarp[(size_t)chunk*(BB*HH*DV) + (b*HH + h)*DV + d] = acc[h];
}

// ---------------- K4a (fused with chunk-reduce): ctx[b,f] = u[b,h,:] @ Wv[f,:] ----------------
__global__ __launch_bounds__(256) void k4a(const float* __restrict__ Wv,
                                           const float* __restrict__ gv,
                                           const float* __restrict__ bv) {
    int h = blockIdx.x, b = blockIdx.y;
    __shared__ float u[DV];
    int tid = threadIdx.x, lane = tid & 31, wid = tid >> 5;
    float t = g_t[b*HH + h];
    int base = (b*HH + h)*DV;
    for (int d = tid; d < DV; d += 256) {
        float s = 0.f;
#pragma unroll
        for (int c = 0; c < NCHUNK; c++) s += g_vbarp[(size_t)c*(BB*HH*DV) + base + d];
        u[d] = gv[d] * (s - t) + bv[d];
    }
    __syncthreads();
    for (int j = wid; j < DH; j += 8) {
        int f = h*DH + j;
        float dot = 0.f;
        for (int d = lane; d < DV; d += 32) dot += u[d] * Wv[(size_t)f*DV + d];
        dot = warp_sum(dot);
        if (lane == 0) g_ctx[b*FF + f] = dot;
    }
}

// ---------------- K4b: attended[b,:] = ctx @ Wo.T + bo ----------------
__global__ __launch_bounds__(256) void k4b(const float* __restrict__ Wo,
                                           const float* __restrict__ bo) {
    int b = blockIdx.x;
    __shared__ float c[FF];
    int tid = threadIdx.x, lane = tid & 31, wid = tid >> 5;
    for (int i = tid; i < FF; i += 256) c[i] = g_ctx[b*FF + i];
    __syncthreads();
    for (int dv = wid; dv < DV; dv += 8) {
        float dot = 0.f;
        for (int f = lane; f < FF; f += 32) dot += c[f] * Wo[(size_t)dv*FF + f];
        dot = warp_sum(dot);
        if (lane == 0) g_att[b*DV + dv] = dot + bo[dv];
    }
}

// ---------------- K5: gate GEMM (mma.sync tf32) + fused sigmoid/residual epilogue ----------------
// out[r,c] = A[r,c] + sigmoid( sum_k A[r,k]*Wg[c,k] + gsem[b,c] ) * att[b,c]
// CTA tile M=128, N=128; K=768 in 24 tiles of 32 (4 k-steps of 8).
// 2-stage cp.async double buffer. 8 warps 2(M)x4(N); warp 64x32 via
// mma.m16n8k8 tf32. smem stride 36 floats -> conflict-free fragment loads.

#define K5_LDA 36
#define K5_TILE_BYTES (128*K5_LDA*4)       // 18432
#define K5_A_OFF(s) ((s)*2*K5_TILE_BYTES)
#define K5_B_OFF(s) ((s)*2*K5_TILE_BYTES + K5_TILE_BYTES)
#define K5_SMEM_TOTAL (4*K5_TILE_BYTES)    // 73728; reused for C staging
#define K5_CS 132

__global__ void __launch_bounds__(256, 2)
k5(const float* __restrict__ A, const float* __restrict__ Wg, float* __restrict__ out) {
    extern __shared__ float smem[];
    uint32_t sbase = smem_u32(smem);
    int tid = threadIdx.x, wid = tid >> 5, lane = tid & 31;
    int rowBase = blockIdx.x * 128;
    int colBase = blockIdx.y * 128;
    int warp_m = wid >> 2;       // 0..1 -> 64 rows
    int warp_n = wid & 3;        // 0..3 -> 32 cols
    int g = lane >> 2, tig = lane & 3;

    uint32_t dsto[4];
    const float* srcA[4];
    const float* srcB[4];
#pragma unroll
    for (int i = 0; i < 4; i++) {
        int idx = tid + i*256;           // 0..1023
        int row = idx >> 3, seg = idx & 7;
        dsto[i] = (uint32_t)((row*K5_LDA + seg*4) * 4);
        srcA[i] = A  + (size_t)(rowBase + row)*DV + seg*4;
        srcB[i] = Wg + (size_t)(colBase + row)*KG + seg*4;
    }

    float cf[4][4][4];
#pragma unroll
    for (int mi = 0; mi < 4; mi++)
#pragma unroll
        for (int ni = 0; ni < 4; ni++)
#pragma unroll
            for (int e = 0; e < 4; e++) cf[mi][ni][e] = 0.f;

    // prologue: stage 0
#pragma unroll
    for (int i = 0; i < 4; i++) {
        CP16(sbase + K5_A_OFF(0) + dsto[i], srcA[i]);
        CP16(sbase + K5_B_OFF(0) + dsto[i], srcB[i]);
    }
    CP_COMMIT();

    int buf = 0;
    for (int kt = 0; kt < 24; kt++) {
        if (kt + 1 < 24) {
#pragma unroll
            for (int i = 0; i < 4; i++) {
                CP16(sbase + K5_A_OFF(buf^1) + dsto[i], srcA[i] + (kt+1)*32);
                CP16(sbase + K5_B_OFF(buf^1) + dsto[i], srcB[i] + (kt+1)*32);
            }
            CP_COMMIT();
            asm volatile("cp.async.wait_group 1;" ::: "memory");
        } else {
            asm volatile("cp.async.wait_group 0;" ::: "memory");
        }
        __syncthreads();

        const float* As = smem + (K5_A_OFF(buf) >> 2);
        const float* Bs = smem + (K5_B_OFF(buf) >> 2);
#pragma unroll
        for (int ks = 0; ks < 4; ks++) {
            int k0 = ks*8;
            uint32_t af[4][4], bfr[4][2];
#pragma unroll
            for (int mi = 0; mi < 4; mi++) {
                int r0 = warp_m*64 + mi*16 + g;
                af[mi][0] = __float_as_uint(As[r0*K5_LDA + k0 + tig]);
                af[mi][1] = __float_as_uint(As[(r0+8)*K5_LDA + k0 + tig]);
                af[mi][2] = __float_as_uint(As[r0*K5_LDA + k0 + tig + 4]);
                af[mi][3] = __float_as_uint(As[(r0+8)*K5_LDA + k0 + tig + 4]);
            }
#pragma unroll
            for (int ni = 0; ni < 4; ni++) {
                int c0 = warp_n*32 + ni*8 + g;
                bfr[ni][0] = __float_as_uint(Bs[c0*K5_LDA + k0 + tig]);
                bfr[ni][1] = __float_as_uint(Bs[c0*K5_LDA + k0 + tig + 4]);
            }
#pragma unroll
            for (int mi = 0; mi < 4; mi++)
#pragma unroll
                for (int ni = 0; ni < 4; ni++)
                    mma_tf32(cf[mi][ni], af[mi], bfr[ni]);
        }
        __syncthreads();
        buf ^= 1;
    }

    // stage accumulators into smem (reuses pipeline smem)
#pragma unroll
    for (int mi = 0; mi < 4; mi++) {
        int r0 = warp_m*64 + mi*16 + g;
#pragma unroll
        for (int ni = 0; ni < 4; ni++) {
            int c0 = warp_n*32 + ni*8 + 2*tig;
            smem[r0*K5_CS + c0]         = cf[mi][ni][0];
            smem[r0*K5_CS + c0 + 1]     = cf[mi][ni][1];
            smem[(r0+8)*K5_CS + c0]     = cf[mi][ni][2];
            smem[(r0+8)*K5_CS + c0 + 1] = cf[mi][ni][3];
        }
    }
    __syncthreads();

    // fused epilogue: 4096 float4, 16 per thread
    int b = rowBase >> 10;
    const float* gs = g_gsem + b*DV;
    const float* at = g_att + b*DV;
#pragma unroll
    for (int j = 0; j < 16; j++) {
        int idx = tid + j*256;          // float4 index
        int row = idx >> 5, c4 = idx & 31;
        int r = rowBase + row;
        int c = colBase + c4*4;
        const float* Cr = smem + row*K5_CS + c4*4;
        float4 av = *(const float4*)(A + (size_t)r*DV + c);
        float4 o;
        o.x = av.x + at[c+0] * (1.f/(1.f + __expf(-(Cr[0] + gs[c+0]))));
        o.y = av.y + at[c+1] * (1.f/(1.f + __expf(-(Cr[1] + gs[c+1]))));
        o.z = av.z + at[c+2] * (1.f/(1.f + __expf(-(Cr[2] + gs[c+2]))));
        o.w = av.w + at[c+3] * (1.f/(1.f + __expf(-(Cr[3] + gs[c+3]))));
        *(float4*)(out + (size_t)r*DV + c) = o;
    }
}

// ---------------- launcher (7 graph nodes) ----------------
extern "C" void kernel_launch(void* const* d_in, const int* in_sizes, int n_in,
                              void* d_out, int out_size) {
    const float* visual   = (const float*)d_in[0];
    const float* semantic = (const float*)d_in[1];
    const float* Wq = (const float*)d_in[2];
    const float* Wk = (const float*)d_in[3];
    const float* Wv = (const float*)d_in[4];
    const float* Wo = (const float*)d_in[5];
    const float* bo = (const float*)d_in[6];
    const float* Wg = (const float*)d_in[7];
    const float* bg = (const float*)d_in[8];
    const float* gv = (const float*)d_in[9];
    const float* bv = (const float*)d_in[10];
    const float* gs = (const float*)d_in[11];
    const float* bs = (const float*)d_in[12];
    float* out = (float*)d_out;

    cudaFuncSetAttribute(k5, cudaFuncAttributeMaxDynamicSharedMemorySize, K5_SMEM_TOTAL);

    k0<<<104, 256>>>(semantic, Wq, Wk, Wg, gv, bv, gs, bs, bg);
    k1<<<ROWS/32, 256>>>(visual);
    k2<<<BB*HH, 256>>>();
    k3<<<dim3(NCHUNK, BB), 768>>>(visual);
    k4a<<<dim3(HH, BB), 256>>>(Wv, gv, bv);
    k4b<<<BB, 256>>>(Wo, bo);
    k5<<<dim3(ROWS/128, DV/128), 256, K5_SMEM_TOTAL>>>(visual, Wg, out);
}

// round 9
// speedup vs baseline: 2.6303x; 1.6971x over previous
#include <cuda_runtime.h>
#include <math.h>
#include <stdint.h>

// ---------------- problem constants ----------------
#define BB 8
#define NN 1024
#define DV 768
#define DS 512
#define FF 768
#define HH 12
#define DH 64
#define KG 1280        // Dv + Ds
#define ROWS (BB*NN)   // 8192
#define SCALE 0.125f   // dh^-0.5
#define EPS 1e-5f

// ---------------- scratch (device globals; no allocation allowed) ----------------
__device__ float g_gw[BB*HH*DV];      // scale * gv[d] * wqk[b,h,d]
__device__ float g_S1[BB*HH];         // sum_d gw
__device__ float g_S0[BB*HH];         // scale * sum_d bv[d]*wqk
__device__ float g_gsem[BB*DV];       // sem @ Wg[:,768:].T + bg
__device__ float g_mu[ROWS];
__device__ float g_rstd[ROWS];
__device__ float g_scores[BB*HH*NN];
__device__ float g_w[BB*HH*NN];       // attn * rstd
__device__ float g_t[BB*HH];          // sum_n attn*rstd*mu
#define NCHUNK 32
__device__ float g_vbarp[NCHUNK*BB*HH*DV];
__device__ float g_ctx[BB*FF];
__device__ float g_att[BB*DV];

// grid barrier state (self-resetting count; monotone sense — replay-safe)
__device__ unsigned g_count = 0;
__device__ unsigned g_sense = 0;

// ---------------- generic helpers ----------------
__device__ __forceinline__ float warp_sum(float v) {
#pragma unroll
    for (int o = 16; o > 0; o >>= 1) v += __shfl_down_sync(0xffffffffu, v, o);
    return v;
}
__device__ __forceinline__ float warp_sum_all(float v) {
#pragma unroll
    for (int o = 16; o > 0; o >>= 1) v += __shfl_xor_sync(0xffffffffu, v, o);
    return v;
}
__device__ __forceinline__ float warp_max(float v) {
#pragma unroll
    for (int o = 16; o > 0; o >>= 1) v = fmaxf(v, __shfl_down_sync(0xffffffffu, v, o));
    return v;
}
__device__ __forceinline__ float block_sum256(float v, float* red) {
    int lane = threadIdx.x & 31, wid = threadIdx.x >> 5;
    __syncthreads();
    v = warp_sum(v);
    if (lane == 0) red[wid] = v;
    __syncthreads();
    if (wid == 0) {
        float x = (lane < 8) ? red[lane] : 0.f;
        x = warp_sum(x);
        if (lane == 0) red[0] = x;
    }
    __syncthreads();
    return red[0];
}
__device__ __forceinline__ float block_max256(float v, float* red) {
    int lane = threadIdx.x & 31, wid = threadIdx.x >> 5;
    __syncthreads();
    v = warp_max(v);
    if (lane == 0) red[wid] = v;
    __syncthreads();
    if (wid == 0) {
        float x = (lane < 8) ? red[lane] : -1e30f;
        x = warp_max(x);
        if (lane == 0) red[0] = x;
    }
    __syncthreads();
    return red[0];
}

#define CP16(dst, src)   asm volatile("cp.async.cg.shared.global [%0], [%1], 16;" :: "r"(dst), "l"(src) : "memory")
#define CP_COMMIT()      asm volatile("cp.async.commit_group;" ::: "memory")

__device__ __forceinline__ uint32_t smem_u32(const void* p) {
    uint32_t a;
    asm("{ .reg .u64 t; cvta.to.shared.u64 t, %1; cvt.u32.u64 %0, t; }" : "=r"(a) : "l"(p));
    return a;
}

// m16n8k8 tf32 mma (row.col), D = A*B + D. Operands hold raw fp32 bits.
__device__ __forceinline__ void mma_tf32(float* c, const uint32_t* a, const uint32_t* b) {
    asm volatile(
        "mma.sync.aligned.m16n8k8.row.col.f32.tf32.tf32.f32 "
        "{%0,%1,%2,%3}, {%4,%5,%6,%7}, {%8,%9}, {%0,%1,%2,%3};"
        : "+f"(c[0]), "+f"(c[1]), "+f"(c[2]), "+f"(c[3])
        : "r"(a[0]), "r"(a[1]), "r"(a[2]), "r"(a[3]), "r"(b[0]), "r"(b[1]));
}

// grid-wide barrier: per-thread fence, block sync, elected arrive + sense wait.
__device__ __forceinline__ void gbar() {
    __threadfence();
    __syncthreads();
    if (threadIdx.x == 0) {
        unsigned s = atomicAdd(&g_sense, 0u);      // read BEFORE arriving
        unsigned old = atomicAdd(&g_count, 1u);
        if (old == gridDim.x - 1) {
            atomicExch(&g_count, 0u);
            __threadfence();
            atomicAdd(&g_sense, 1u);
        } else {
            while (atomicAdd(&g_sense, 0u) == s) __nanosleep(64);
        }
        __threadfence();
    }
    __syncthreads();
}

// ---------------- K5 tile constants ----------------
#define K5_LDA 36
#define K5_TILE_BYTES (128*K5_LDA*4)       // 18432
#define K5_A_OFF(s) ((s)*2*K5_TILE_BYTES)
#define K5_B_OFF(s) ((s)*2*K5_TILE_BYTES + K5_TILE_BYTES)
#define MEGA_SMEM (4*K5_TILE_BYTES)        // 73728; aliased by gw_s / C staging
#define K5_CS 132

// ================= persistent megakernel =================
__global__ void __launch_bounds__(256, 2)
mega(const float* __restrict__ vis, const float* __restrict__ sem,
     const float* __restrict__ Wq, const float* __restrict__ Wk,
     const float* __restrict__ Wv, const float* __restrict__ Wo,
     const float* __restrict__ bo, const float* __restrict__ Wg,
     const float* __restrict__ bg, const float* __restrict__ gv,
     const float* __restrict__ bv, const float* __restrict__ gs,
     const float* __restrict__ bs, float* __restrict__ out)
{
    extern __shared__ float smem[];
    __shared__ float sm[DS];
    __shared__ float red[8];
    __shared__ float qh[DH];
    __shared__ float s1s[HH], s0s[HH];
    __shared__ float ws[HH][32];
    __shared__ float u[DV];
    int tid = threadIdx.x, lane = tid & 31, wid = tid >> 5;
    int G = gridDim.x;

    // ---------- P0: semantic LN + q_h -> gw/S1/S0 ; gsem ----------
    for (int blk = blockIdx.x; blk < 104; blk += G) {
        if (blk < 96) {
            int b = blk / 12, h = blk % 12;
            float sum = 0.f, sq = 0.f;
            for (int i = tid; i < DS; i += 256) {
                float v = sem[b*DS + i];
                sm[i] = v; sum += v; sq += v*v;
            }
            sum = block_sum256(sum, red);
            sq  = block_sum256(sq, red);
            float mu = sum * (1.f/DS);
            float rstd = rsqrtf(sq * (1.f/DS) - mu*mu + EPS);
            for (int i = tid; i < DS; i += 256)
                sm[i] = (sm[i] - mu) * rstd * gs[i] + bs[i];
            __syncthreads();
            for (int j = wid; j < DH; j += 8) {
                int f = h*DH + j;
                float dot = 0.f;
                for (int s = lane; s < DS; s += 32) dot += sm[s] * Wq[(size_t)f*DS + s];
                dot = warp_sum(dot);
                if (lane == 0) qh[j] = dot;
            }
            __syncthreads();
            float s1p = 0.f, s0p = 0.f;
            for (int d = tid; d < DV; d += 256) {
                float s = 0.f;
#pragma unroll 16
                for (int j = 0; j < DH; j++) s += qh[j] * Wk[(size_t)(h*DH + j)*DV + d];
                s *= SCALE;
                float gwv = gv[d] * s;
                g_gw[(b*HH + h)*DV + d] = gwv;
                s1p += gwv;
                s0p += bv[d] * s;
            }
            s1p = block_sum256(s1p, red);
            s0p = block_sum256(s0p, red);
            if (tid == 0) { g_S1[b*HH + h] = s1p; g_S0[b*HH + h] = s0p; }
            __syncthreads();
        } else {
            int b = blk - 96;
            for (int i = tid; i < DS; i += 256) sm[i] = sem[b*DS + i];
            __syncthreads();
            for (int dv = wid; dv < DV; dv += 8) {
                float dot = 0.f;
                for (int s = lane; s < DS; s += 32) dot += sm[s] * Wg[(size_t)dv*KG + DV + s];
                dot = warp_sum(dot);
                if (lane == 0) g_gsem[b*DV + dv] = dot + bg[dv];
            }
            __syncthreads();
        }
    }
    gbar();

    // ---------- P1: visual LN stats + scores (32 rows/task) ----------
    for (int task = blockIdx.x; task < ROWS/32; task += G) {
        float* gw_s = smem;      // 36 KB alias
        int row0 = task * 32;
        int b = row0 >> 10;
        {
            const float4* gsrc = (const float4*)(g_gw + b*HH*DV);
            float4* gdst = (float4*)gw_s;
#pragma unroll
            for (int i = 0; i < 9; i++) gdst[tid + i*256] = gsrc[tid + i*256];
        }
        if (tid < HH) { s1s[tid] = g_S1[b*HH + tid]; s0s[tid] = g_S0[b*HH + tid]; }
        __syncthreads();
#pragma unroll
        for (int rr = 0; rr < 4; rr++) {
            int row = row0 + wid*4 + rr;
            const float4* x4 = (const float4*)(vis + (size_t)row * DV);
            float4 xv[6];
#pragma unroll
            for (int s = 0; s < 6; s++) xv[s] = x4[s*32 + lane];
            float sum = 0.f, sq = 0.f;
#pragma unroll
            for (int s = 0; s < 6; s++) {
                sum += xv[s].x + xv[s].y + xv[s].z + xv[s].w;
                sq  += xv[s].x*xv[s].x + xv[s].y*xv[s].y + xv[s].z*xv[s].z + xv[s].w*xv[s].w;
            }
            sum = warp_sum_all(sum);
            sq  = warp_sum_all(sq);
            float mu = sum * (1.f/DV);
            float rstd = rsqrtf(sq * (1.f/DV) - mu*mu + EPS);
            if (lane == 0) { g_mu[row] = mu; g_rstd[row] = rstd; }
            int n = row & (NN - 1);
#pragma unroll 2
            for (int h = 0; h < HH; h++) {
                const float4* g4 = (const float4*)(gw_s + h*DV);
                float dot = 0.f;
#pragma unroll
                for (int s = 0; s < 6; s++) {
                    float4 gv4 = g4[s*32 + lane];
                    dot += xv[s].x*gv4.x + xv[s].y*gv4.y + xv[s].z*gv4.z + xv[s].w*gv4.w;
                }
                dot = warp_sum(dot);
                if (lane == 0)
                    g_scores[(b*HH + h)*NN + n] = rstd * (dot - mu*s1s[h]) + s0s[h];
            }
        }
        __syncthreads();
    }
    gbar();

    // ---------- P2: softmax; w = attn*rstd, t ----------
    for (int bh = blockIdx.x; bh < BB*HH; bh += G) {
        int b = bh / HH;
        float loc[4];
        float mx = -1e30f;
#pragma unroll
        for (int i = 0; i < 4; i++) {
            loc[i] = g_scores[bh*NN + tid + i*256];
            mx = fmaxf(mx, loc[i]);
        }
        mx = block_max256(mx, red);
        float s = 0.f;
#pragma unroll
        for (int i = 0; i < 4; i++) { loc[i] = expf(loc[i] - mx); s += loc[i]; }
        s = block_sum256(s, red);
        float inv = 1.f / s;
        float tp = 0.f;
#pragma unroll
        for (int i = 0; i < 4; i++) {
            int n = tid + i*256;
            float a = loc[i] * inv;
            float rs = g_rstd[b*NN + n];
            float w = a * rs;
            g_w[bh*NN + n] = w;
            tp += w * g_mu[b*NN + n];
        }
        tp = block_sum256(tp, red);
        if (tid == 0) g_t[bh] = tp;
        __syncthreads();
    }
    gbar();

    // ---------- P3: per-chunk partial vbar (256 threads, 3 slices) ----------
    for (int task = blockIdx.x; task < NCHUNK*BB; task += G) {
        int chunk = task & (NCHUNK - 1);
        int b = task >> 5;
        int n0 = chunk * 32;
        for (int i = tid; i < HH*32; i += 256) {       // FIX: full 384-entry load
            ws[i >> 5][i & 31] = g_w[(b*HH + (i >> 5))*NN + n0 + (i & 31)];
        }
        __syncthreads();
#pragma unroll
        for (int sl = 0; sl < 3; sl++) {
            int d = sl*256 + tid;
            float acc[HH];
#pragma unroll
            for (int h = 0; h < HH; h++) acc[h] = 0.f;
            const float* base = vis + ((size_t)(b << 10) + n0) * DV + d;
#pragma unroll 4
            for (int j = 0; j < 32; j++) {
                float x = base[(size_t)j * DV];
#pragma unroll
                for (int h = 0; h < HH; h++) acc[h] += ws[h][j] * x;
            }
#pragma unroll
            for (int h = 0; h < HH; h++)
                g_vbarp[(size_t)chunk*(BB*HH*DV) + (b*HH + h)*DV + d] = acc[h];
        }
        __syncthreads();
    }
    gbar();

    // ---------- P4: chunk-reduce + u + ctx ----------
    for (int task = blockIdx.x; task < BB*HH; task += G) {
        int h = task % HH, b = task / HH;
        float t = g_t[b*HH + h];
        int base = (b*HH + h)*DV;
        for (int d = tid; d < DV; d += 256) {
            float s = 0.f;
#pragma unroll
            for (int c = 0; c < NCHUNK; c++) s += g_vbarp[(size_t)c*(BB*HH*DV) + base + d];
            u[d] = gv[d] * (s - t) + bv[d];
        }
        __syncthreads();
        for (int j = wid; j < DH; j += 8) {
            int f = h*DH + j;
            float dot = 0.f;
            for (int d = lane; d < DV; d += 32) dot += u[d] * Wv[(size_t)f*DV + d];
            dot = warp_sum(dot);
            if (lane == 0) g_ctx[b*FF + f] = dot;
        }
        __syncthreads();
    }
    gbar();

    // ---------- P5: attended = ctx @ Wo.T + bo ----------
    for (int b = blockIdx.x; b < BB; b += G) {
        for (int i = tid; i < FF; i += 256) u[i] = g_ctx[b*FF + i];
        __syncthreads();
        for (int dv = wid; dv < DV; dv += 8) {
            float dot = 0.f;
            for (int f = lane; f < FF; f += 32) dot += u[f] * Wo[(size_t)dv*FF + f];
            dot = warp_sum(dot);
            if (lane == 0) g_att[b*DV + dv] = dot + bo[dv];
        }
        __syncthreads();
    }
    gbar();

    // ---------- P6: gate GEMM (tf32 mma) + fused epilogue ----------
    for (int task = blockIdx.x; task < 384; task += G) {
        uint32_t sbase = smem_u32(smem);
        int rowBase = (task & 63) * 128;
        int colBase = (task >> 6) * 128;
        int warp_m = wid >> 2;
        int warp_n = wid & 3;
        int g = lane >> 2, tig = lane & 3;

        uint32_t dsto[4];
        const float* srcA[4];
        const float* srcB[4];
#pragma unroll
        for (int i = 0; i < 4; i++) {
            int idx = tid + i*256;
            int row = idx >> 3, seg = idx & 7;
            dsto[i] = (uint32_t)((row*K5_LDA + seg*4) * 4);
            srcA[i] = vis + (size_t)(rowBase + row)*DV + seg*4;
            srcB[i] = Wg  + (size_t)(colBase + row)*KG + seg*4;
        }

        float cf[4][4][4];
#pragma unroll
        for (int mi = 0; mi < 4; mi++)
#pragma unroll
            for (int ni = 0; ni < 4; ni++)
#pragma unroll
                for (int e = 0; e < 4; e++) cf[mi][ni][e] = 0.f;

#pragma unroll
        for (int i = 0; i < 4; i++) {
            CP16(sbase + K5_A_OFF(0) + dsto[i], srcA[i]);
            CP16(sbase + K5_B_OFF(0) + dsto[i], srcB[i]);
        }
        CP_COMMIT();

        int buf = 0;
        for (int kt = 0; kt < 24; kt++) {
            if (kt + 1 < 24) {
#pragma unroll
                for (int i = 0; i < 4; i++) {
                    CP16(sbase + K5_A_OFF(buf^1) + dsto[i], srcA[i] + (kt+1)*32);
                    CP16(sbase + K5_B_OFF(buf^1) + dsto[i], srcB[i] + (kt+1)*32);
                }
                CP_COMMIT();
                asm volatile("cp.async.wait_group 1;" ::: "memory");
            } else {
                asm volatile("cp.async.wait_group 0;" ::: "memory");
            }
            __syncthreads();

            const float* As = smem + (K5_A_OFF(buf) >> 2);
            const float* Bs = smem + (K5_B_OFF(buf) >> 2);
#pragma unroll
            for (int ks = 0; ks < 4; ks++) {
                int k0 = ks*8;
                uint32_t af[4][4], bfr[4][2];
#pragma unroll
                for (int mi = 0; mi < 4; mi++) {
                    int r0 = warp_m*64 + mi*16 + g;
                    af[mi][0] = __float_as_uint(As[r0*K5_LDA + k0 + tig]);
                    af[mi][1] = __float_as_uint(As[(r0+8)*K5_LDA + k0 + tig]);
                    af[mi][2] = __float_as_uint(As[r0*K5_LDA + k0 + tig + 4]);
                    af[mi][3] = __float_as_uint(As[(r0+8)*K5_LDA + k0 + tig + 4]);
                }
#pragma unroll
                for (int ni = 0; ni < 4; ni++) {
                    int c0 = warp_n*32 + ni*8 + g;
                    bfr[ni][0] = __float_as_uint(Bs[c0*K5_LDA + k0 + tig]);
                    bfr[ni][1] = __float_as_uint(Bs[c0*K5_LDA + k0 + tig + 4]);
                }
#pragma unroll
                for (int mi = 0; mi < 4; mi++)
#pragma unroll
                    for (int ni = 0; ni < 4; ni++)
                        mma_tf32(cf[mi][ni], af[mi], bfr[ni]);
            }
            __syncthreads();
            buf ^= 1;
        }

        // stage accumulators into smem
#pragma unroll
        for (int mi = 0; mi < 4; mi++) {
            int r0 = warp_m*64 + mi*16 + g;
#pragma unroll
            for (int ni = 0; ni < 4; ni++) {
                int c0 = warp_n*32 + ni*8 + 2*tig;
                smem[r0*K5_CS + c0]         = cf[mi][ni][0];
                smem[r0*K5_CS + c0 + 1]     = cf[mi][ni][1];
                smem[(r0+8)*K5_CS + c0]     = cf[mi][ni][2];
                smem[(r0+8)*K5_CS + c0 + 1] = cf[mi][ni][3];
            }
        }
        __syncthreads();

        int b = rowBase >> 10;
        const float* gsp = g_gsem + b*DV;
        const float* at = g_att + b*DV;
#pragma unroll
        for (int j = 0; j < 16; j++) {
            int idx = tid + j*256;
            int row = idx >> 5, c4 = idx & 31;
            int r = rowBase + row;
            int c = colBase + c4*4;
            const float* Cr = smem + row*K5_CS + c4*4;
            float4 av = *(const float4*)(vis + (size_t)r*DV + c);
            float4 o;
            o.x = av.x + at[c+0] * (1.f/(1.f + __expf(-(Cr[0] + gsp[c+0]))));
            o.y = av.y + at[c+1] * (1.f/(1.f + __expf(-(Cr[1] + gsp[c+1]))));
            o.z = av.z + at[c+2] * (1.f/(1.f + __expf(-(Cr[2] + gsp[c+2]))));
            o.w = av.w + at[c+3] * (1.f/(1.f + __expf(-(Cr[3] + gsp[c+3]))));
            *(float4*)(out + (size_t)r*DV + c) = o;
        }
        __syncthreads();    // smem reused if this block takes another tile
    }
}

// ---------------- launcher (single graph node) ----------------
extern "C" void kernel_launch(void* const* d_in, const int* in_sizes, int n_in,
                              void* d_out, int out_size) {
    const float* visual   = (const float*)d_in[0];
    const float* semantic = (const float*)d_in[1];
    const float* Wq = (const float*)d_in[2];
    const float* Wk = (const float*)d_in[3];
    const float* Wv = (const float*)d_in[4];
    const float* Wo = (const float*)d_in[5];
    const float* bo = (const float*)d_in[6];
    const float* Wg = (const float*)d_in[7];
    const float* bg = (const float*)d_in[8];
    const float* gv = (const float*)d_in[9];
    const float* bv = (const float*)d_in[10];
    const float* gs = (const float*)d_in[11];
    const float* bs = (const float*)d_in[12];
    float* out = (float*)d_out;

    cudaFuncSetAttribute(mega, cudaFuncAttributeMaxDynamicSharedMemorySize, MEGA_SMEM);

    int dev = 0;
    cudaGetDevice(&dev);
    int nsm = 148;
    cudaDeviceGetAttribute(&nsm, cudaDevAttrMultiProcessorCount, dev);
    int occ = 0;
    cudaOccupancyMaxActiveBlocksPerMultiprocessor(&occ, mega, 256, MEGA_SMEM);
    if (occ < 1) occ = 1;
    int G = nsm * occ;

    mega<<<G, 256, MEGA_SMEM>>>(visual, semantic, Wq, Wk, Wv, Wo, bo,
                                Wg, bg, gv, bv, gs, bs, out);
}